// round 9
// baseline (speedup 1.0000x reference)
#include <cuda_runtime.h>
#include <cuda_bf16.h>

// Problem constants
#define BS1 32
#define BS2 128
#define NUM_EC 64
#define MEM_DIM 256
#define MLP_DIM 256
#define Q_DIM 256           // 4 * CONV_DIM

// Scratch (device globals — allocation is forbidden)
__device__ float g_att[BS1 * NUM_EC];              // softmax_e(criteria·Wa_c)
__device__ float g_PC [BS1 * NUM_EC * MLP_DIM];    // raw criteria @ Wm_c
__device__ float g_PE [BS2 * MLP_DIM];             // ehr @ Wm_e

// ---- PDL primitives ----
__device__ __forceinline__ void pdl_trigger() {
    asm volatile("griddepcontrol.launch_dependents;");
}
__device__ __forceinline__ void pdl_wait() {
    asm volatile("griddepcontrol.wait;" ::: "memory");
}

__device__ __forceinline__ void fma4(float4& a, float s, const float4& w) {
    a.x = fmaf(s, w.x, a.x); a.y = fmaf(s, w.y, a.y);
    a.z = fmaf(s, w.z, a.z); a.w = fmaf(s, w.w, a.w);
}

// ---------------------------------------------------------------------------
// Prep kernel, 320 blocks:
//   bids [0,256):   PC[b,e,d] = dot(criteria[b,e,:], Wm_c[:,d])
//     NEW SHAPE: register d-tiling. Block = (b, tile of 8 e), all 256 d.
//     Thread (dgrp = tid&63 -> d0 = dgrp*4, kh = tid>>6 -> k-quarter).
//     Each thread: acc[8e][4d]; one broadcast LDS.128 of criteria feeds
//     16 FMA (was 4) -> smem traffic 4x lower; W read as coalesced float4
//     rows, reused across 8 e in registers. k-partials reduced via smem.
//   bids [256,288): att[b,:] = softmax_e(criteria[b,e,:]·Wa_c)
//                   (logit_e[p] and b_align are constant over e -> cancel)
//   bids [288,320): PE[p,d] = dot(ehr[p,:], Wm_e[:,d])   (4 p / block)
// ---------------------------------------------------------------------------
#define C1_BLOCKS   256
#define ATT_BLOCKS  32
#define PE_BLOCKS   32
#define E_TILE      8
#define PE_P_TILE   4

__global__ void __launch_bounds__(256) k_prep(const float* __restrict__ ehr,
                                              const float* __restrict__ crit,
                                              const float* __restrict__ W_align,
                                              const float* __restrict__ W_mlp) {
    __shared__ __align__(16) float sbuf[8192];   // 32 KB (criteria 8KB / partials 32KB)
    const int bid = blockIdx.x;
    const int tid = threadIdx.x;

    if (bid < C1_BLOCKS) {
        // ----- PC -----
        const int b  = bid >> 3;
        const int e0 = (bid & 7) * E_TILE;
        const int d0 = (tid & 63) * 4;     // this thread's 4 d-columns
        const int kh = tid >> 6;           // k-quarter (0..3), 64 k each

        // load criteria[b, e0..e0+7, 0..255]  (512 float4, 2 per thread)
        const float4* src = (const float4*)(crit + (size_t)(b * NUM_EC + e0) * Q_DIM);
        ((float4*)sbuf)[tid]       = src[tid];
        ((float4*)sbuf)[tid + 256] = src[tid + 256];
        __syncthreads();

        const float4* cs4 = (const float4*)sbuf;    // [E_TILE][64]

        float4 acc[E_TILE];
        #pragma unroll
        for (int e = 0; e < E_TILE; ++e) acc[e] = make_float4(0.f, 0.f, 0.f, 0.f);

        // k loop over this thread's quarter: 16 groups of 4 k
        #pragma unroll 2
        for (int j = 0; j < 16; ++j) {
            const int k = kh * 64 + j * 4;
            const float4 w0 = *(const float4*)(W_mlp + (size_t)(k + 0) * MLP_DIM + d0);
            const float4 w1 = *(const float4*)(W_mlp + (size_t)(k + 1) * MLP_DIM + d0);
            const float4 w2 = *(const float4*)(W_mlp + (size_t)(k + 2) * MLP_DIM + d0);
            const float4 w3 = *(const float4*)(W_mlp + (size_t)(k + 3) * MLP_DIM + d0);
            #pragma unroll
            for (int e = 0; e < E_TILE; ++e) {
                const float4 c = cs4[e * 64 + kh * 16 + j];  // warp-broadcast LDS
                fma4(acc[e], c.x, w0);
                fma4(acc[e], c.y, w1);
                fma4(acc[e], c.z, w2);
                fma4(acc[e], c.w, w3);
            }
        }
        __syncthreads();                   // criteria consumed; reuse as partials

        // partials: [4 kh][8 e][256 d]
        float* part = sbuf;
        #pragma unroll
        for (int e = 0; e < E_TILE; ++e)
            *(float4*)(part + ((kh * E_TILE + e) * 256 + d0)) = acc[e];
        __syncthreads();

        // 2048 outputs, 256 threads -> 8 each (coalesced over d)
        #pragma unroll
        for (int i = 0; i < 8; ++i) {
            const int idx = tid + i * 256;        // e*256 + d
            const int e = idx >> 8;
            const int d = idx & 255;
            float v = part[(0 * E_TILE + e) * 256 + d]
                    + part[(1 * E_TILE + e) * 256 + d]
                    + part[(2 * E_TILE + e) * 256 + d]
                    + part[(3 * E_TILE + e) * 256 + d];
            g_PC[((size_t)(b * NUM_EC + e0 + e)) * MLP_DIM + d] = v;
        }
        pdl_trigger();

    } else if (bid < C1_BLOCKS + ATT_BLOCKS) {
        // ----- att -----
        const int b = bid - C1_BLOCKS;
        const int e = tid >> 2;
        const int q = tid & 3;

        const float4* row = (const float4*)(crit + ((size_t)(b * NUM_EC + e)) * Q_DIM);
        const float4* wa  = (const float4*)W_align;

        float s = 0.f;
        #pragma unroll
        for (int i = 0; i < 16; ++i) {
            float4 c = row[q * 16 + i];
            float4 w = wa [q * 16 + i];
            s += c.x * w.x + c.y * w.y + c.z * w.z + c.w * w.w;
        }
        s += __shfl_xor_sync(0xffffffffu, s, 1);
        s += __shfl_xor_sync(0xffffffffu, s, 2);

        float* sm = sbuf;
        if (q == 0) sm[e] = s;
        __syncthreads();

        if (tid < 32) {
            float a  = sm[tid];
            float bb = sm[tid + 32];
            float m = fmaxf(a, bb);
            #pragma unroll
            for (int off = 16; off; off >>= 1)
                m = fmaxf(m, __shfl_xor_sync(0xffffffffu, m, off));
            float ea = expf(a - m);
            float eb = expf(bb - m);
            float ss = ea + eb;
            #pragma unroll
            for (int off = 16; off; off >>= 1)
                ss += __shfl_xor_sync(0xffffffffu, ss, off);
            float inv = 1.f / ss;
            g_att[b * NUM_EC + tid]      = ea * inv;
            g_att[b * NUM_EC + tid + 32] = eb * inv;
        }
        __syncthreads();
        pdl_trigger();

    } else {
        // ----- PE -----
        const int pg = bid - (C1_BLOCKS + ATT_BLOCKS);
        const int p0 = pg * PE_P_TILE;
        const int d  = tid;

        float* es = sbuf;                  // [PE_P_TILE][MEM_DIM]
        #pragma unroll
        for (int i = 0; i < PE_P_TILE; ++i)
            es[i * MEM_DIM + d] = ehr[(size_t)(p0 + i) * MEM_DIM + d];
        __syncthreads();

        float acc[PE_P_TILE];
        #pragma unroll
        for (int i = 0; i < PE_P_TILE; ++i) acc[i] = 0.f;

        const float* w = W_mlp + (size_t)Q_DIM * MLP_DIM + d;
        #pragma unroll 4
        for (int k = 0; k < MEM_DIM; ++k) {
            float wv = w[(size_t)k * MLP_DIM];
            #pragma unroll
            for (int i = 0; i < PE_P_TILE; ++i)
                acc[i] += es[i * MEM_DIM + k] * wv;
        }
        #pragma unroll
        for (int i = 0; i < PE_P_TILE; ++i)
            g_PE[(size_t)(p0 + i) * MLP_DIM + d] = acc[i];
        pdl_trigger();
    }
}

// ---------------------------------------------------------------------------
// Main (store-bound; UNCHANGED from R8 — 44.7us, at write ceiling).
// out[b,p,e,d] = att[b,e] * (PC[b,e,d] + PE[p,d]) + b_mlp[d]
// grid = 32 b x 32 p-groups (P_TILE=4), block = 256, PDL wait before
// touching prep outputs.
// ---------------------------------------------------------------------------
#define P_TILE 4
__global__ void __launch_bounds__(256) k_main(float* __restrict__ out,
                                              const float* __restrict__ b_mlp) {
    const int b   = blockIdx.x >> 5;
    const int pg  = blockIdx.x & 31;
    const int p0  = pg * P_TILE;
    const int tid = threadIdx.x;
    const int v   = tid & 63;

    // Prologue on inputs only (safe before the dependency resolves)
    const float4 bm = __ldg((const float4*)b_mlp + v);
    float4* o = (float4*)out;
    const size_t base = (size_t)b * (BS2 * NUM_EC * (MLP_DIM / 4))
                      + (size_t)p0 * (NUM_EC * (MLP_DIM / 4));
    const int stride_p = NUM_EC * (MLP_DIM / 4);    // 4096 float4

    pdl_wait();

    __shared__ float atts[NUM_EC];
    if (tid < NUM_EC) atts[tid] = g_att[b * NUM_EC + tid];
    __syncthreads();

    const float4 pe0 = __ldg((const float4*)g_PE + (size_t)(p0 + 0) * (MLP_DIM / 4) + v);
    const float4 pe1 = __ldg((const float4*)g_PE + (size_t)(p0 + 1) * (MLP_DIM / 4) + v);
    const float4 pe2 = __ldg((const float4*)g_PE + (size_t)(p0 + 2) * (MLP_DIM / 4) + v);
    const float4 pe3 = __ldg((const float4*)g_PE + (size_t)(p0 + 3) * (MLP_DIM / 4) + v);

    const float4* pc = (const float4*)g_PC + (size_t)b * NUM_EC * (MLP_DIM / 4);

    #pragma unroll 4
    for (int k = 0; k < 16; ++k) {
        const int i = tid + k * 256;
        const float  a = atts[i >> 6];
        const float4 c = __ldg(&pc[i]);
        float4 r0, r1, r2, r3;
        r0.x = fmaf(a, c.x + pe0.x, bm.x); r0.y = fmaf(a, c.y + pe0.y, bm.y);
        r0.z = fmaf(a, c.z + pe0.z, bm.z); r0.w = fmaf(a, c.w + pe0.w, bm.w);
        r1.x = fmaf(a, c.x + pe1.x, bm.x); r1.y = fmaf(a, c.y + pe1.y, bm.y);
        r1.z = fmaf(a, c.z + pe1.z, bm.z); r1.w = fmaf(a, c.w + pe1.w, bm.w);
        r2.x = fmaf(a, c.x + pe2.x, bm.x); r2.y = fmaf(a, c.y + pe2.y, bm.y);
        r2.z = fmaf(a, c.z + pe2.z, bm.z); r2.w = fmaf(a, c.w + pe2.w, bm.w);
        r3.x = fmaf(a, c.x + pe3.x, bm.x); r3.y = fmaf(a, c.y + pe3.y, bm.y);
        r3.z = fmaf(a, c.z + pe3.z, bm.z); r3.w = fmaf(a, c.w + pe3.w, bm.w);
        __stcs(&o[base + 0 * stride_p + i], r0);
        __stcs(&o[base + 1 * stride_p + i], r1);
        __stcs(&o[base + 2 * stride_p + i], r2);
        __stcs(&o[base + 3 * stride_p + i], r3);
    }
}

// ---------------------------------------------------------------------------
// Inputs per metadata order:
// 0: ehr_vector (128*256)  1: criteria (32*64*256)  2: ec_mask (unused)
// 3: W_align (512)         4: b_align (unused, cancels in softmax)
// 5: W_mlp (512*256)       6: b_mlp (256)
// ---------------------------------------------------------------------------
extern "C" void kernel_launch(void* const* d_in, const int* in_sizes, int n_in,
                              void* d_out, int out_size) {
    const float* ehr     = (const float*)d_in[0];
    const float* crit    = (const float*)d_in[1];
    const float* W_align = (const float*)d_in[3];
    const float* W_mlp   = (const float*)d_in[5];
    const float* b_mlp   = (const float*)d_in[6];
    float* out = (float*)d_out;

    k_prep<<<C1_BLOCKS + ATT_BLOCKS + PE_BLOCKS, 256>>>(ehr, crit, W_align, W_mlp);

    cudaLaunchConfig_t cfg = {};
    cfg.gridDim  = dim3(BS1 * (BS2 / P_TILE), 1, 1);
    cfg.blockDim = dim3(256, 1, 1);
    cudaLaunchAttribute attrs[1];
    attrs[0].id = cudaLaunchAttributeProgrammaticStreamSerialization;
    attrs[0].val.programmaticStreamSerializationAllowed = 1;
    cfg.attrs = attrs;
    cfg.numAttrs = 1;
    cudaLaunchKernelEx(&cfg, k_main, out, (const float*)b_mlp);
}

// round 10
// speedup vs baseline: 1.0750x; 1.0750x over previous
#include <cuda_runtime.h>
#include <cuda_bf16.h>

// Problem constants
#define BS1 32
#define BS2 128
#define NUM_EC 64
#define MEM_DIM 256
#define MLP_DIM 256
#define Q_DIM 256           // 4 * CONV_DIM

// Scratch (device globals — allocation is forbidden)
__device__ float g_att[BS1 * NUM_EC];              // softmax_e(criteria·Wa_c)
__device__ float g_PC [BS1 * NUM_EC * MLP_DIM];    // raw criteria @ Wm_c
__device__ float g_PE [BS2 * MLP_DIM];             // ehr @ Wm_e

// ---- PDL primitives ----
__device__ __forceinline__ void pdl_trigger() {
    asm volatile("griddepcontrol.launch_dependents;");
}
__device__ __forceinline__ void pdl_wait() {
    asm volatile("griddepcontrol.wait;" ::: "memory");
}

// ---- packed f32x2 helpers ----
__device__ __forceinline__ unsigned long long pk2(float lo, float hi) {
    unsigned long long r;
    asm("mov.b64 %0, {%1, %2};" : "=l"(r)
        : "r"(__float_as_uint(lo)), "r"(__float_as_uint(hi)));
    return r;
}
__device__ __forceinline__ unsigned long long fma2(unsigned long long a,
                                                   unsigned long long b,
                                                   unsigned long long c) {
    unsigned long long d;
    asm("fma.rn.f32x2 %0, %1, %2, %3;" : "=l"(d) : "l"(a), "l"(b), "l"(c));
    return d;
}
__device__ __forceinline__ float2 upk2(unsigned long long v) {
    unsigned int lo, hi;
    asm("mov.b64 {%0, %1}, %2;" : "=r"(lo), "=r"(hi) : "l"(v));
    return make_float2(__uint_as_float(lo), __uint_as_float(hi));
}

// ---------------------------------------------------------------------------
// Prep kernel, 320 blocks:
//   bids [0,256):   PC[b,e,d] = dot(criteria[b,e,:], Wm_c[:,d])
//     Block = (b, e-tile of 16, d-half of 128)  -> W L2 traffic 32 MB total.
//     Thread = (d0: 32 groups of 4 d, es: 4 groups of 4 e, kh: k-half).
//     FMA2 paired across d: W float4 rows give (d0,d1),(d2,d3) packs free;
//     criteria scalar dup'd via 1 MOV per (e,k) on the idle alu pipe.
//     Per thread: 1024 FMA2, 128 LDS.128 (broadcast), 128 LDG.128 (L1-hit).
//     k-half partials reduced via smem.
//   bids [256,288): att[b,:] = softmax_e(criteria[b,e,:]·Wa_c)
//                   (logit_e[p] and b_align are constant over e -> cancel)
//   bids [288,320): PE[p,d] = dot(ehr[p,:], Wm_e[:,d])   (4 p / block)
// ---------------------------------------------------------------------------
#define C1_BLOCKS   256
#define ATT_BLOCKS  32
#define PE_BLOCKS   32
#define E_TILE      16
#define PE_P_TILE   4

__global__ void __launch_bounds__(256) k_prep(const float* __restrict__ ehr,
                                              const float* __restrict__ crit,
                                              const float* __restrict__ W_align,
                                              const float* __restrict__ W_mlp) {
    __shared__ __align__(16) float sbuf[E_TILE * Q_DIM];   // 16 KB, reused
    const int bid = blockIdx.x;
    const int tid = threadIdx.x;

    if (bid < C1_BLOCKS) {
        // ----- PC -----
        const int b   = bid >> 3;
        const int et  = (bid >> 1) & 3;
        const int dh  = bid & 1;
        const int e0  = et * E_TILE;
        const int dg  = tid & 31;          // d-group (4 d each)
        const int es  = (tid >> 5) & 3;    // e-subtile (4 e each)
        const int kh  = tid >> 7;          // k-half (0/1)
        const int dloc = dg * 4;           // d within the 128-wide half
        const int d0  = dh * 128 + dloc;   // global d

        // load criteria[b, e0..e0+15, 0..255]  (1024 float4, 4 per thread)
        float4* cs = (float4*)sbuf;        // [E_TILE][64]
        const float4* src = (const float4*)(crit + (size_t)(b * NUM_EC + e0) * Q_DIM);
        #pragma unroll
        for (int i = 0; i < 4; ++i)
            cs[tid + i * 256] = src[tid + i * 256];
        __syncthreads();

        // acc[4 e][4 d] as f32x2 pairs: (d0,d0+1) and (d0+2,d0+3)
        unsigned long long acc01[4], acc23[4];
        #pragma unroll
        for (int e = 0; e < 4; ++e) { acc01[e] = 0ull; acc23[e] = 0ull; }

        const int k4base = kh * 32;
        #pragma unroll 2
        for (int j = 0; j < 32; ++j) {
            const int k4 = k4base + j;
            const int k  = k4 * 4;
            // 4 W rows (coalesced 512B per row across the warp; L1-hot across es)
            const float4 w0 = *(const float4*)(W_mlp + (size_t)(k + 0) * MLP_DIM + d0);
            const float4 w1 = *(const float4*)(W_mlp + (size_t)(k + 1) * MLP_DIM + d0);
            const float4 w2 = *(const float4*)(W_mlp + (size_t)(k + 2) * MLP_DIM + d0);
            const float4 w3 = *(const float4*)(W_mlp + (size_t)(k + 3) * MLP_DIM + d0);
            const unsigned long long w0a = pk2(w0.x, w0.y), w0b = pk2(w0.z, w0.w);
            const unsigned long long w1a = pk2(w1.x, w1.y), w1b = pk2(w1.z, w1.w);
            const unsigned long long w2a = pk2(w2.x, w2.y), w2b = pk2(w2.z, w2.w);
            const unsigned long long w3a = pk2(w3.x, w3.y), w3b = pk2(w3.z, w3.w);
            #pragma unroll
            for (int e = 0; e < 4; ++e) {
                const float4 c = cs[(es * 4 + e) * 64 + k4];  // broadcast LDS.128
                unsigned long long cx = pk2(c.x, c.x);
                unsigned long long cy = pk2(c.y, c.y);
                unsigned long long cz = pk2(c.z, c.z);
                unsigned long long cw = pk2(c.w, c.w);
                acc01[e] = fma2(cx, w0a, acc01[e]);
                acc23[e] = fma2(cx, w0b, acc23[e]);
                acc01[e] = fma2(cy, w1a, acc01[e]);
                acc23[e] = fma2(cy, w1b, acc23[e]);
                acc01[e] = fma2(cz, w2a, acc01[e]);
                acc23[e] = fma2(cz, w2b, acc23[e]);
                acc01[e] = fma2(cw, w3a, acc01[e]);
                acc23[e] = fma2(cw, w3b, acc23[e]);
            }
        }
        __syncthreads();                   // criteria consumed; reuse as partials

        // partials: [2 kh][16 e][128 dloc]  = 16 KB
        float* part = sbuf;
        #pragma unroll
        for (int e = 0; e < 4; ++e) {
            const float2 a = upk2(acc01[e]);
            const float2 b2 = upk2(acc23[e]);
            float* p = part + ((kh * E_TILE + es * 4 + e) * 128 + dloc);
            p[0] = a.x; p[1] = a.y; p[2] = b2.x; p[3] = b2.y;
        }
        __syncthreads();

        // 2048 outputs, 256 threads -> 8 each (coalesced over dd)
        #pragma unroll
        for (int i = 0; i < 8; ++i) {
            const int idx = tid + i * 256;         // e*128 + dd
            const int e  = idx >> 7;
            const int dd = idx & 127;
            float v = part[e * 128 + dd] + part[(E_TILE + e) * 128 + dd];
            g_PC[((size_t)(b * NUM_EC + e0 + e)) * MLP_DIM + dh * 128 + dd] = v;
        }
        pdl_trigger();

    } else if (bid < C1_BLOCKS + ATT_BLOCKS) {
        // ----- att -----
        const int b = bid - C1_BLOCKS;
        const int e = tid >> 2;
        const int q = tid & 3;

        const float4* row = (const float4*)(crit + ((size_t)(b * NUM_EC + e)) * Q_DIM);
        const float4* wa  = (const float4*)W_align;

        float s = 0.f;
        #pragma unroll
        for (int i = 0; i < 16; ++i) {
            float4 c = row[q * 16 + i];
            float4 w = wa [q * 16 + i];
            s += c.x * w.x + c.y * w.y + c.z * w.z + c.w * w.w;
        }
        s += __shfl_xor_sync(0xffffffffu, s, 1);
        s += __shfl_xor_sync(0xffffffffu, s, 2);

        float* sm = sbuf;
        if (q == 0) sm[e] = s;
        __syncthreads();

        if (tid < 32) {
            float a  = sm[tid];
            float bb = sm[tid + 32];
            float m = fmaxf(a, bb);
            #pragma unroll
            for (int off = 16; off; off >>= 1)
                m = fmaxf(m, __shfl_xor_sync(0xffffffffu, m, off));
            float ea = expf(a - m);
            float eb = expf(bb - m);
            float ss = ea + eb;
            #pragma unroll
            for (int off = 16; off; off >>= 1)
                ss += __shfl_xor_sync(0xffffffffu, ss, off);
            float inv = 1.f / ss;
            g_att[b * NUM_EC + tid]      = ea * inv;
            g_att[b * NUM_EC + tid + 32] = eb * inv;
        }
        __syncthreads();
        pdl_trigger();

    } else {
        // ----- PE -----
        const int pg = bid - (C1_BLOCKS + ATT_BLOCKS);
        const int p0 = pg * PE_P_TILE;
        const int d  = tid;

        float* es = sbuf;                  // [PE_P_TILE][MEM_DIM]
        #pragma unroll
        for (int i = 0; i < PE_P_TILE; ++i)
            es[i * MEM_DIM + d] = ehr[(size_t)(p0 + i) * MEM_DIM + d];
        __syncthreads();

        float acc[PE_P_TILE];
        #pragma unroll
        for (int i = 0; i < PE_P_TILE; ++i) acc[i] = 0.f;

        const float* w = W_mlp + (size_t)Q_DIM * MLP_DIM + d;
        #pragma unroll 4
        for (int k = 0; k < MEM_DIM; ++k) {
            float wv = w[(size_t)k * MLP_DIM];
            #pragma unroll
            for (int i = 0; i < PE_P_TILE; ++i)
                acc[i] += es[i * MEM_DIM + k] * wv;
        }
        #pragma unroll
        for (int i = 0; i < PE_P_TILE; ++i)
            g_PE[(size_t)(p0 + i) * MLP_DIM + d] = acc[i];
        pdl_trigger();
    }
}

// ---------------------------------------------------------------------------
// Main (store-bound; UNCHANGED — best measured 41.5us, at write ceiling).
// out[b,p,e,d] = att[b,e] * (PC[b,e,d] + PE[p,d]) + b_mlp[d]
// grid = 32 b x 32 p-groups (P_TILE=4), block = 256, PDL wait before
// touching prep outputs.
// ---------------------------------------------------------------------------
#define P_TILE 4
__global__ void __launch_bounds__(256) k_main(float* __restrict__ out,
                                              const float* __restrict__ b_mlp) {
    const int b   = blockIdx.x >> 5;
    const int pg  = blockIdx.x & 31;
    const int p0  = pg * P_TILE;
    const int tid = threadIdx.x;
    const int v   = tid & 63;

    // Prologue on inputs only (safe before the dependency resolves)
    const float4 bm = __ldg((const float4*)b_mlp + v);
    float4* o = (float4*)out;
    const size_t base = (size_t)b * (BS2 * NUM_EC * (MLP_DIM / 4))
                      + (size_t)p0 * (NUM_EC * (MLP_DIM / 4));
    const int stride_p = NUM_EC * (MLP_DIM / 4);    // 4096 float4

    pdl_wait();

    __shared__ float atts[NUM_EC];
    if (tid < NUM_EC) atts[tid] = g_att[b * NUM_EC + tid];
    __syncthreads();

    const float4 pe0 = __ldg((const float4*)g_PE + (size_t)(p0 + 0) * (MLP_DIM / 4) + v);
    const float4 pe1 = __ldg((const float4*)g_PE + (size_t)(p0 + 1) * (MLP_DIM / 4) + v);
    const float4 pe2 = __ldg((const float4*)g_PE + (size_t)(p0 + 2) * (MLP_DIM / 4) + v);
    const float4 pe3 = __ldg((const float4*)g_PE + (size_t)(p0 + 3) * (MLP_DIM / 4) + v);

    const float4* pc = (const float4*)g_PC + (size_t)b * NUM_EC * (MLP_DIM / 4);

    #pragma unroll 4
    for (int k = 0; k < 16; ++k) {
        const int i = tid + k * 256;
        const float  a = atts[i >> 6];
        const float4 c = __ldg(&pc[i]);
        float4 r0, r1, r2, r3;
        r0.x = fmaf(a, c.x + pe0.x, bm.x); r0.y = fmaf(a, c.y + pe0.y, bm.y);
        r0.z = fmaf(a, c.z + pe0.z, bm.z); r0.w = fmaf(a, c.w + pe0.w, bm.w);
        r1.x = fmaf(a, c.x + pe1.x, bm.x); r1.y = fmaf(a, c.y + pe1.y, bm.y);
        r1.z = fmaf(a, c.z + pe1.z, bm.z); r1.w = fmaf(a, c.w + pe1.w, bm.w);
        r2.x = fmaf(a, c.x + pe2.x, bm.x); r2.y = fmaf(a, c.y + pe2.y, bm.y);
        r2.z = fmaf(a, c.z + pe2.z, bm.z); r2.w = fmaf(a, c.w + pe2.w, bm.w);
        r3.x = fmaf(a, c.x + pe3.x, bm.x); r3.y = fmaf(a, c.y + pe3.y, bm.y);
        r3.z = fmaf(a, c.z + pe3.z, bm.z); r3.w = fmaf(a, c.w + pe3.w, bm.w);
        __stcs(&o[base + 0 * stride_p + i], r0);
        __stcs(&o[base + 1 * stride_p + i], r1);
        __stcs(&o[base + 2 * stride_p + i], r2);
        __stcs(&o[base + 3 * stride_p + i], r3);
    }
}

// ---------------------------------------------------------------------------
// Inputs per metadata order:
// 0: ehr_vector (128*256)  1: criteria (32*64*256)  2: ec_mask (unused)
// 3: W_align (512)         4: b_align (unused, cancels in softmax)
// 5: W_mlp (512*256)       6: b_mlp (256)
// ---------------------------------------------------------------------------
extern "C" void kernel_launch(void* const* d_in, const int* in_sizes, int n_in,
                              void* d_out, int out_size) {
    const float* ehr     = (const float*)d_in[0];
    const float* crit    = (const float*)d_in[1];
    const float* W_align = (const float*)d_in[3];
    const float* W_mlp   = (const float*)d_in[5];
    const float* b_mlp   = (const float*)d_in[6];
    float* out = (float*)d_out;

    k_prep<<<C1_BLOCKS + ATT_BLOCKS + PE_BLOCKS, 256>>>(ehr, crit, W_align, W_mlp);

    cudaLaunchConfig_t cfg = {};
    cfg.gridDim  = dim3(BS1 * (BS2 / P_TILE), 1, 1);
    cfg.blockDim = dim3(256, 1, 1);
    cudaLaunchAttribute attrs[1];
    attrs[0].id = cudaLaunchAttributeProgrammaticStreamSerialization;
    attrs[0].val.programmaticStreamSerializationAllowed = 1;
    cfg.attrs = attrs;
    cfg.numAttrs = 1;
    cudaLaunchKernelEx(&cfg, k_main, out, (const float*)b_mlp);
}